// round 17
// baseline (speedup 1.0000x reference)
#include <cuda_runtime.h>
#include <cuda_bf16.h>
#include <cstdint>

// ResRnn via warp-level bf16 mma.sync. R17: one global barrier per STEP.
// ph1->ph2 handoff via distributed per-CTA produce-flags: consumer warp jg
// spins on its 8 producer CTAs only (H cols 256jg..+256 <= ns' in [8jg,8jg+8)),
// so stragglers pipeline instead of serializing 2x per step. End-of-step
// global barrier bounds skew (keeps single-buffer H and S/g_Sf race-free).
// Everything else = R16: 128 CTAs (4 M-slices x 32 N-slices) x 512 thr,
// A bf16-hi LDG.128 ring depth 4, W1 hi+lo / W2 hi in SMEM, fp32 master.

#define SEQ    1024
#define BATCH  256
#define INSZ   64
#define SSZ    1024
#define OUTSZ  64
#define NCTA   128
#define NTHR   512
#define NSL    32
#define NSTEP  16

// SMEM layout (bytes): 3 W planes (32 rows x 2048B, XOR-swizzled)
#define W1HB   0u
#define W1LB   65536u
#define W2HB   131072u
#define WCH23  32768u
#define RED    196608u
#define BIAS1  221184u
#define BIAS2  221312u
#define SMEM_BYTES 221440u

// Fragment-permuted state (bf16-hi): [buf][mtile 16][ktile 64][lane*4+reg]
__device__ uint32_t g_SP[2][16][64][128];
__device__ uint32_t g_HP[16][64][128];
__device__ float    g_Sf[2][BATCH][SSZ];
__device__ unsigned g_grp[16];
__device__ unsigned g_root;
__device__ unsigned g_pflag[NCTA];       // per-CTA monotonic produce counter
__device__ volatile unsigned g_epoch;

// ---------------- PTX helpers ----------------
__device__ __forceinline__ uint32_t smem_u32(const void* p) {
    uint32_t a;
    asm("{ .reg .u64 t; cvta.to.shared.u64 t, %1; cvt.u32.u64 %0, t; }"
        : "=r"(a) : "l"(p));
    return a;
}
__device__ __forceinline__ void ldsm4(uint32_t a[4], uint32_t addr) {
    asm volatile("ldmatrix.sync.aligned.m8n8.x4.shared.b16 {%0,%1,%2,%3}, [%4];"
        : "=r"(a[0]), "=r"(a[1]), "=r"(a[2]), "=r"(a[3]) : "r"(addr));
}
__device__ __forceinline__ void mma16816(float c[4], const uint4& a,
                                         uint32_t b0, uint32_t b1) {
    asm volatile(
        "mma.sync.aligned.m16n8k16.row.col.f32.bf16.bf16.f32 "
        "{%0,%1,%2,%3}, {%4,%5,%6,%7}, {%8,%9}, {%0,%1,%2,%3};"
        : "+f"(c[0]), "+f"(c[1]), "+f"(c[2]), "+f"(c[3])
        : "r"(a.x), "r"(a.y), "r"(a.z), "r"(a.w), "r"(b0), "r"(b1));
}

// 2-level tree barrier (16 groups x 8), monotonic (graph-replay safe)
__device__ __forceinline__ void gbar(unsigned ep0, unsigned idx, int cta) {
    __syncthreads();
    if (threadIdx.x == 0) {
        __threadfence();
        unsigned o = atomicAdd(&g_grp[cta & 15], 1u);
        if ((o & 7u) == 7u) {
            unsigned r = atomicAdd(&g_root, 1u);
            if ((r & 15u) == 15u) {
                __threadfence();
                atomicAdd((unsigned*)&g_epoch, 1u);
            }
        }
        while ((unsigned)(g_epoch - ep0) < idx) { }
        __threadfence();
    }
    __syncthreads();
}

__device__ __forceinline__ void split_bf(float v, __nv_bfloat16& h, __nv_bfloat16& l) {
    h = __float2bfloat16(v);
    l = __float2bfloat16(v - __bfloat162float(h));
}
__device__ __forceinline__ uint32_t pk(__nv_bfloat16 a, __nv_bfloat16 b) {
    return (uint32_t)__bfloat16_as_ushort(a) | ((uint32_t)__bfloat16_as_ushort(b) << 16);
}
__device__ __forceinline__ uint32_t pkf(float a, float b) {
    return pk(__float2bfloat16(a), __float2bfloat16(b));
}

// One warp's M=16 x N=32 x K=256 slice. A via depth-4 LDG.128 ring.
template <int PASSES>
__device__ __forceinline__ void mma_phase(const uint4* __restrict__ pa,
                                          uint32_t whl, uint32_t wll,
                                          uint32_t nx, uint32_t c16b,
                                          float acc[4][4])
{
#pragma unroll
    for (int i = 0; i < 4; ++i)
#pragma unroll
        for (int j = 0; j < 4; ++j) acc[i][j] = 0.0f;

    uint4 A[4];
#pragma unroll
    for (int i = 0; i < 4; ++i) A[i] = pa[i * 32];

#pragma unroll
    for (int st = 0; st < NSTEP; ++st) {
        const int s = st & 3;
        const uint32_t sw = (((c16b + 2u * (uint32_t)st) ^ nx) << 4);
        uint32_t WhA[4], WhB[4];
        ldsm4(WhA, whl + sw);
        ldsm4(WhB, whl + WCH23 + sw);
        const uint4 a = A[s];
        if (st + 4 < NSTEP) A[s] = pa[(st + 4) * 32];
        mma16816(acc[0], a, WhA[0], WhA[1]);
        mma16816(acc[1], a, WhA[2], WhA[3]);
        mma16816(acc[2], a, WhB[0], WhB[1]);
        mma16816(acc[3], a, WhB[2], WhB[3]);
        if (PASSES == 2) {
            uint32_t WlA[4], WlB[4];
            ldsm4(WlA, wll + sw);
            ldsm4(WlB, wll + WCH23 + sw);
            mma16816(acc[0], a, WlA[0], WlA[1]);
            mma16816(acc[1], a, WlA[2], WlA[3]);
            mma16816(acc[2], a, WlB[0], WlB[1]);
            mma16816(acc[3], a, WlB[2], WlB[3]);
        }
    }
}

// Balanced 4-way K-reduction: group jg ends with the full sum for acc[jg].
__device__ __forceinline__ void kreduce(uint32_t su, int jg, int mg, int lane,
                                        float acc[4][4]) {
#pragma unroll
    for (int a = 0; a < 4; ++a) {
        if (a == jg) continue;
        const int p = jg - (jg > a ? 1 : 0);
        const uint32_t o = su + RED +
            (uint32_t)(((a * 3 + p) * 128) + mg * 32 + lane) * 16u;
        asm volatile("st.shared.v4.f32 [%0], {%1,%2,%3,%4};" ::
            "r"(o), "f"(acc[a][0]), "f"(acc[a][1]),
            "f"(acc[a][2]), "f"(acc[a][3]));
    }
    __syncthreads();
#pragma unroll
    for (int p = 0; p < 3; ++p) {
        const uint32_t o = su + RED +
            (uint32_t)(((jg * 3 + p) * 128) + mg * 32 + lane) * 16u;
        float r0, r1, r2, r3;
        asm volatile("ld.shared.v4.f32 {%0,%1,%2,%3}, [%4];"
            : "=f"(r0), "=f"(r1), "=f"(r2), "=f"(r3) : "r"(o));
        acc[jg][0] += r0; acc[jg][1] += r1;
        acc[jg][2] += r2; acc[jg][3] += r3;
    }
}

__global__ __launch_bounds__(NTHR, 1)
void resrnn_kernel(const float* __restrict__ x,
                   const float* __restrict__ W1,
                   const float* __restrict__ b1,
                   const float* __restrict__ W2,
                   const float* __restrict__ b2,
                   float* __restrict__ out)
{
    extern __shared__ char smem[];
    const uint32_t su = smem_u32(smem);

    const int tid  = threadIdx.x;
    const int wid  = tid >> 5;
    const int lane = tid & 31;
    const int mg   = wid & 3;
    const int jg   = wid >> 2;
    const int cta  = blockIdx.x;
    const int ms   = cta & 3;
    const int ns   = cta >> 2;
    const int n0   = ns * NSL;
    const int mt   = 4 * ms + mg;

    const unsigned ep0 = g_epoch;

    // Capture flag baselines for this warp's 8 ph2-producers BEFORE init gbar
    // (all flags equal at launch start; must read before any producer bumps).
    unsigned f0 = 0; int pfi = 0;
    if (lane < 8) {
        pfi = ((8 * jg + lane) << 2) | ms;
        f0  = *(volatile unsigned*)&g_pflag[pfi];
    }

    // ---- stage W slices: W1 hi+lo, W2 hi (2048B rows + XOR-16B swizzle) ----
    for (int idx = tid; idx < NSL * SSZ; idx += NTHR) {
        int n = idx >> 10, k = idx & (SSZ - 1);
        uint32_t o = (uint32_t)n * 2048u
                   + (uint32_t)(((k >> 3) ^ (n & 7)) << 4)
                   + (uint32_t)((k & 7) << 1);
        float w1 = W1[(size_t)(n0 + n) * SSZ + k];
        __nv_bfloat16 wh, wl; split_bf(w1, wh, wl);
        *(__nv_bfloat16*)(smem + W1HB + o) = wh;
        *(__nv_bfloat16*)(smem + W1LB + o) = wl;
        float w2 = W2[(size_t)(n0 + n) * SSZ + k];
        *(__nv_bfloat16*)(smem + W2HB + o) = __float2bfloat16(w2);
    }
    {
        float* b1s = (float*)(smem + BIAS1);
        float* b2s = (float*)(smem + BIAS2);
        if (tid < NSL) { b1s[tid] = b1[n0 + tid]; b2s[tid] = b2[n0 + tid]; }
    }

    // ---- init S0 (this CTA's 64 rows x 32 cols): [x0, zeros] ----
    for (int idx = tid; idx < 64 * 16; idx += NTHR) {
        int row = idx >> 4, pc = idx & 15;
        int b = 64 * ms + row, k = n0 + 2 * pc;
        float v0 = (k < INSZ)     ? x[(size_t)b * INSZ + k]     : 0.0f;
        float v1 = (k + 1 < INSZ) ? x[(size_t)b * INSZ + k + 1] : 0.0f;
        *(float2*)&g_Sf[0][b][k] = make_float2(v0, v1);
        int bt = b >> 4, rr = b & 15, c = k & 15;
        int lt  = (rr & 7) * 4 + ((c >> 1) & 3);
        int reg = (rr >> 3) + 2 * (c >> 3);
        g_SP[0][bt][k >> 4][lt * 4 + reg] = pkf(v0, v1);
    }
    unsigned bc = 0;
    gbar(ep0, ++bc, cta);

    // ---- per-lane constants ----
    const int lane4 = lane * 4;
    const uint32_t wn   = (uint32_t)((lane & 7) + ((lane >> 4) & 1) * 8);
    const uint32_t nx   = wn & 7u;
    const uint32_t wrow = wn * 2048u;
    const uint32_t c16b = (uint32_t)jg * 32u + (uint32_t)((lane >> 3) & 1);

    const int gr = lane >> 2;
    const int gc = 2 * (lane & 3);
    const float* b1s = (const float*)(smem + BIAS1);
    const float* b2s = (const float*)(smem + BIAS2);
    const float p = 0.97f;
    const float q = 1.0f - 0.97f;
    const int ep_lt = gr * 4 + (lane & 3);
    const int no   = jg & 1;
    const int cown = 8 * jg + gc;

    for (int t = 0; t < SEQ; ++t) {
        const int cur = t & 1, nxt = (t + 1) & 1;

        // ============ Phase 1: H = |S @ W1^T + b1| ============
        {
            float acc[4][4];
            mma_phase<2>((const uint4*)&g_SP[cur][mt][jg * 16][lane4],
                         su + W1HB + wrow, su + W1LB + wrow, nx, c16b, acc);
            kreduce(su, jg, mg, lane, acc);
            const int kt = 2 * ns + (jg >> 1);
            uint32_t* hp = &g_HP[mt][kt][ep_lt * 4];
#pragma unroll
            for (int h = 0; h < 2; ++h) {
                float v0 = fabsf(acc[jg][2 * h]     + b1s[cown]);
                float v1 = fabsf(acc[jg][2 * h + 1] + b1s[cown + 1]);
                hp[h + 2 * no] = pkf(v0, v1);
            }
        }
        // ---- release: H slice written -> bump this CTA's produce flag ----
        __threadfence();
        __syncthreads();          // also separates RED reuse (ph1 vs ph2 kreduce)
        if (tid == 0) atomicAdd(&g_pflag[cta], 1u);

        // ---- acquire: wait for the 8 producers of THIS warp's K-quarter ----
        if (lane < 8) {
            const unsigned tgt = (unsigned)(t + 1);
            while (((*(volatile unsigned*)&g_pflag[pfi]) - f0) < tgt) { }
        }
        __syncwarp();
        __threadfence();

        // ============ Phase 2: S' = p*S + q*(H @ W2^T + b2) ============
        {
            float acc[4][4];
            mma_phase<1>((const uint4*)&g_HP[mt][jg * 16][lane4],
                         su + W2HB + wrow, 0u, nx, c16b, acc);
            kreduce(su, jg, mg, lane, acc);
            if (n0 < SSZ - INSZ) {
                const int kt = 2 * ns + 4 + (jg >> 1);
                uint32_t* sp = &g_SP[nxt][mt][kt][ep_lt * 4];
#pragma unroll
                for (int h = 0; h < 2; ++h) {
                    int b = 64 * ms + 16 * mg + gr + h * 8;
                    float2 sold = *(const float2*)&g_Sf[cur][b][n0 + cown];
                    float n0v = p * sold.x + q * (acc[jg][2 * h]     + b2s[cown]);
                    float n1v = p * sold.y + q * (acc[jg][2 * h + 1] + b2s[cown + 1]);
                    *(float2*)&g_Sf[nxt][b][n0 + INSZ + cown] = make_float2(n0v, n1v);
                    sp[h + 2 * no] = pkf(n0v, n1v);
                }
            } else if (t == SEQ - 1) {
#pragma unroll
                for (int h = 0; h < 2; ++h) {
                    int b = 64 * ms + 16 * mg + gr + h * 8;
                    float2 sold = *(const float2*)&g_Sf[cur][b][n0 + cown];
                    float n0v = p * sold.x + q * (acc[jg][2 * h]     + b2s[cown]);
                    float n1v = p * sold.y + q * (acc[jg][2 * h + 1] + b2s[cown + 1]);
                    *(float2*)&out[(size_t)b * OUTSZ + (n0 - (SSZ - OUTSZ)) + cown] =
                        make_float2(n0v, n1v);
                }
            }
            // x_{t+1} injection: CTAs ns<2 fill cols [32ns, +32) of own rows
            if (t + 1 < SEQ && ns < 2) {
                const float* xp = x + (size_t)(t + 1) * BATCH * INSZ;
                for (int idx = tid; idx < 64 * 16; idx += NTHR) {
                    int row = idx >> 4, pc = idx & 15;
                    int b = 64 * ms + row, k = n0 + 2 * pc;
                    float v0 = xp[(size_t)b * INSZ + k];
                    float v1 = xp[(size_t)b * INSZ + k + 1];
                    *(float2*)&g_Sf[nxt][b][k] = make_float2(v0, v1);
                    int bt = b >> 4, rr = b & 15, c = k & 15;
                    int lt  = (rr & 7) * 4 + ((c >> 1) & 3);
                    int reg = (rr >> 3) + 2 * (c >> 3);
                    g_SP[nxt][bt][k >> 4][lt * 4 + reg] = pkf(v0, v1);
                }
            }
        }
        // ---- ONE global barrier per step (bounds skew; guards S/g_Sf/H reuse)
        gbar(ep0, ++bc, cta);
    }
}

extern "C" void kernel_launch(void* const* d_in, const int* in_sizes, int n_in,
                              void* d_out, int out_size) {
    (void)in_sizes; (void)n_in; (void)out_size;
    const float* x  = (const float*)d_in[0];
    const float* W1 = (const float*)d_in[1];
    const float* b1 = (const float*)d_in[2];
    const float* W2 = (const float*)d_in[3];
    const float* b2 = (const float*)d_in[4];

    cudaFuncSetAttribute(resrnn_kernel,
                         cudaFuncAttributeMaxDynamicSharedMemorySize,
                         (int)SMEM_BYTES);
    resrnn_kernel<<<NCTA, NTHR, SMEM_BYTES>>>(x, W1, b1, W2, b2, (float*)d_out);
}